// round 5
// baseline (speedup 1.0000x reference)
#include <cuda_runtime.h>

// MultiStageFIRFilter: y = x + sum_{a=1..20} xa_a,
//   xa_a[b,t] = (1/a) * sum_{k=0..24} mc[b,t,k] * xa_{a-1}[b,t-k]  (xa_0 = x, causal)
//
// Fused halo-recompute kernel, warp-pipelined: NO __syncthreads in the stage
// loop. Warp w at stage a waits (acquire) for warp w-1 to finish stage a-1,
// and (anti-dep, 3-deep ring) for warp w+1 to finish stage a-2 before
// overwriting stage a-3's buffer. R=4 positions/thread, 256 threads.

#define NB      4
#define NT      16384
#define M       25
#define STAGES  20
#define HALO    480       // STAGES * (M-1)
#define THREADS 256
#define R       4
#define EXT     1024      // THREADS * R
#define TILE    544       // EXT - HALO
#define PAD     24
#define NTILES  31        // ceil(16384 / 544)
#define NWARP   8
#define RB      (PAD + EXT)   // 1048 floats per ring slot (16B-aligned stride)

__device__ __forceinline__ void flag_release(int* p, int v) {
    asm volatile("st.release.cta.b32 [%0], %1;" :: "l"(p), "r"(v) : "memory");
}
__device__ __forceinline__ int flag_acquire(const int* p) {
    int v;
    asm volatile("ld.acquire.cta.b32 %0, [%1];" : "=r"(v) : "l"(p) : "memory");
    return v;
}

__global__ __launch_bounds__(THREADS, 1)
void fir_kernel(const float* __restrict__ x, const float* __restrict__ mc,
                float* __restrict__ out)
{
    __shared__ __align__(16) float ring[3][RB];
    __shared__ int flags[NWARP];

    const int tile = blockIdx.x % NTILES;
    const int b    = blockIdx.x / NTILES;
    const int t0   = tile * TILE;
    const int tid  = threadIdx.x;
    const int w    = tid >> 5;
    const int lane = tid & 31;
    const int i0   = R * tid;              // local position (multiple of 4)
    const int p0   = t0 - HALO + i0;       // global time of first owned position
    const size_t rowbase = (size_t)b * NT;

    if (tid < PAD) { ring[0][tid] = 0.0f; ring[1][tid] = 0.0f; ring[2][tid] = 0.0f; }
    if (tid < NWARP) flags[tid] = 0;       // flag[w] = last completed stage of warp w

    // ---- per-position coefficients in registers: c[25*r + k] = mc[p0+r][k] ----
    float c[100];
    if (p0 >= 0 && p0 + R - 1 < NT) {
        const float4* g = (const float4*)(mc + (rowbase + (size_t)p0) * M);  // 16B-aligned
        #pragma unroll
        for (int k = 0; k < 25; k++) {
            float4 v4 = g[k];
            c[4*k] = v4.x; c[4*k+1] = v4.y; c[4*k+2] = v4.z; c[4*k+3] = v4.w;
        }
    } else {
        #pragma unroll
        for (int r = 0; r < R; r++) {
            const int p = p0 + r;
            if (p >= 0 && p < NT) {
                const float* g = mc + (rowbase + (size_t)p) * M;
                #pragma unroll
                for (int k = 0; k < 25; k++) c[25*r + k] = g[k];
            } else {
                #pragma unroll
                for (int k = 0; k < 25; k++) c[25*r + k] = 0.0f;
            }
        }
    }

    // ---- stage 0: xa = x ----
    float v[R], y[R];
    if (p0 >= 0 && p0 + R - 1 < NT) {
        const float4 xv = *(const float4*)(x + rowbase + p0);
        v[0] = xv.x; v[1] = xv.y; v[2] = xv.z; v[3] = xv.w;
    } else {
        #pragma unroll
        for (int r = 0; r < R; r++) {
            const int p = p0 + r;
            v[r] = (p >= 0 && p < NT) ? x[rowbase + p] : 0.0f;
        }
    }
    #pragma unroll
    for (int r = 0; r < R; r++) y[r] = v[r];

    *((float4*)(&ring[0][PAD + i0])) = make_float4(v[0], v[1], v[2], v[3]);
    __syncthreads();   // stage-0 data + flag init visible to all warps

    const bool ghost = (p0 < 0);   // t<0 positions stay exactly 0 (tile 0 only)

    #pragma unroll
    for (int a = 1; a <= STAGES; a++) {
        const float inv = 1.0f / (float)a;          // compile-time constant
        const bool warp_active = (32 * w + 31 >= 6 * a);
        if (warp_active) {
            // producer wait: warp w-1 finished stage a-1
            if (w > 0) while (flag_acquire(&flags[w - 1]) < a - 1) {}
            // anti-dep wait: warp w+1 done reading ring[(a-3)%3] (== ring[a%3])
            if (a >= 3 && w < NWARP - 1) while (flag_acquire(&flags[w + 1]) < a - 2) {}

            if (tid >= 6 * a) {                     // exactness trim
                const float* cur = &ring[(a - 1) % 3][0];
                // w24[j] = xa_{a-1}[position i0-24+j]; pos q at smem PAD+q
                float w24[24];
                const float4* wp = (const float4*)(cur + i0);   // PAD + i0 - 24
                #pragma unroll
                for (int j = 0; j < 6; j++) {
                    float4 q = wp[j];
                    w24[4*j] = q.x; w24[4*j+1] = q.y; w24[4*j+2] = q.z; w24[4*j+3] = q.w;
                }

                float acc[R];
                #pragma unroll
                for (int r = 0; r < R; r++) {
                    float pA = 0.0f, pB = 0.0f;
                    #pragma unroll
                    for (int k = 0; k <= 12; k++) {
                        const int d = r - k;
                        const float val = (d >= 0) ? v[d] : w24[24 + d];
                        pA = fmaf(c[25*r + k], val, pA);
                    }
                    #pragma unroll
                    for (int k = 13; k <= 24; k++) {
                        pB = fmaf(c[25*r + k], w24[24 + r - k], pB);
                    }
                    acc[r] = (pA + pB) * inv;
                }
                if (ghost) {
                    #pragma unroll
                    for (int r = 0; r < R; r++) acc[r] = 0.0f;
                }
                #pragma unroll
                for (int r = 0; r < R; r++) { y[r] += acc[r]; v[r] = acc[r]; }
                *((float4*)(&ring[a % 3][PAD + i0])) = make_float4(v[0], v[1], v[2], v[3]);
            }
        }
        __syncwarp();                               // lanes' stores precede release
        if (lane == 0) flag_release(&flags[w], a);  // publish stage a complete
    }

    // ---- write owned (non-halo) outputs ----
    if (i0 >= HALO && p0 < NT) {
        if (p0 + R - 1 < NT) {
            *((float4*)(out + rowbase + p0)) = make_float4(y[0], y[1], y[2], y[3]);
        } else {
            #pragma unroll
            for (int r = 0; r < R; r++)
                if (p0 + r < NT) out[rowbase + p0 + r] = y[r];
        }
    }
}

extern "C" void kernel_launch(void* const* d_in, const int* in_sizes, int n_in,
                              void* d_out, int out_size)
{
    const float* x  = (const float*)d_in[0];   // (4, 16384) float32
    const float* mc = (const float*)d_in[1];   // (4, 16384, 25) float32
    float* out = (float*)d_out;                // (4, 16384) float32
    fir_kernel<<<NB * NTILES, THREADS>>>(x, mc, out);
}